// round 3
// baseline (speedup 1.0000x reference)
#include <cuda_runtime.h>

// Problem constants (fixed by the dataset)
#define P        576          // feature columns
#define P4       144          // P / 4 (float4 groups per row)
#define NB       444          // grid: 148 SMs * 3 CTAs @ 576 thr (also 37*12)
#define NGRP     37           // fold groups
#define BPB      12           // blocks per group

// Deterministic scratch (no allocation): __device__ globals (zero-initialized).
__device__ float g_p1[NB * P];
__device__ float g_p2[NB * P];
__device__ float g_m1[NGRP * P];
__device__ float g_m2[NGRP * P];
__device__ unsigned int g_cnt1[NGRP];   // per-group arrival counters
__device__ unsigned int g_cnt2;         // group-finisher counter

// ---------------------------------------------------------------------------
// Single fused kernel, deadlock-free without any co-residency assumption:
// "last arriver does the fold" (threadfence-reduction pattern). The block
// that observes the final arrival only proceeds because all producers have
// already completed, so no spin-wait on an unscheduled CTA can occur.
//
// Phase 1 (all 444 blocks): one-pass streaming reduction of X.
// Phase 2 (last arriver of each 12-block group): fold 12 partials -> 1.
// Phase 3 (last group finisher): fold 37 -> 1, finalize cumulants, project,
//          reset counters for the next graph replay.
// Fold order is fixed by index -> bitwise-deterministic output.
// ---------------------------------------------------------------------------
__global__ __launch_bounds__(P, 3)
void k_fused(const float* __restrict__ X,
             const float* __restrict__ mu,
             const float* __restrict__ W,
             float* __restrict__ out, int n_rows) {
    const int tx = threadIdx.x % P4;     // float4 column group
    const int ty = threadIdx.x / P4;     // row phase 0..3
    const int c  = threadIdx.x;          // column id for reductions
    const float4* __restrict__ X4 = reinterpret_cast<const float4*>(X);

    __shared__ float sh[4 * P];          // 9216B; reused in phase 3
    __shared__ int s_last;

    // ---------------- Phase 1: stream X (HBM-roofline bound) ----------------
    float s1x = 0.f, s1y = 0.f, s1z = 0.f, s1w = 0.f;
    float s2x = 0.f, s2y = 0.f, s2z = 0.f, s2w = 0.f;

    #pragma unroll 4
    for (int r = blockIdx.x * 4 + ty; r < n_rows; r += NB * 4) {
        float4 v = __ldg(&X4[r * P4 + tx]);
        s1x += v.x; s1y += v.y; s1z += v.z; s1w += v.w;
        s2x += v.x * v.x; s2y += v.y * v.y;
        s2z += v.z * v.z; s2w += v.w * v.w;
    }

    const int cbase = tx * 4;
    // reduce S1 across the 4 row phases
    sh[ty * P + cbase + 0] = s1x;
    sh[ty * P + cbase + 1] = s1y;
    sh[ty * P + cbase + 2] = s1z;
    sh[ty * P + cbase + 3] = s1w;
    __syncthreads();
    g_p1[blockIdx.x * P + c] = sh[c] + sh[P + c] + sh[2 * P + c] + sh[3 * P + c];
    __syncthreads();
    // reduce S2
    sh[ty * P + cbase + 0] = s2x;
    sh[ty * P + cbase + 1] = s2y;
    sh[ty * P + cbase + 2] = s2z;
    sh[ty * P + cbase + 3] = s2w;
    __syncthreads();
    g_p2[blockIdx.x * P + c] = sh[c] + sh[P + c] + sh[2 * P + c] + sh[3 * P + c];

    // ---------------- Phase 2: last arriver of each group folds -------------
    const int g = blockIdx.x / BPB;

    __threadfence();                     // make partials visible before arrive
    __syncthreads();                     // all threads' stores included
    if (threadIdx.x == 0) {
        unsigned int prev = atomicAdd(&g_cnt1[g], 1u);
        s_last = (prev == BPB - 1);
    }
    __syncthreads();
    if (!s_last) return;

    {
        float a = 0.f, b = 0.f;
        #pragma unroll
        for (int i = 0; i < BPB; ++i) {
            const int bb = g * BPB + i;
            a += g_p1[bb * P + c];
            b += g_p2[bb * P + c];
        }
        g_m1[g * P + c] = a;
        g_m2[g * P + c] = b;
    }

    // ---------------- Phase 3: last group finisher finalizes ----------------
    __threadfence();
    __syncthreads();
    if (threadIdx.x == 0) {
        unsigned int prev = atomicAdd(&g_cnt2, 1u);
        s_last = (prev == NGRP - 1);
    }
    __syncthreads();
    if (!s_last) return;

    {
        float S1 = 0.f, S2 = 0.f;
        #pragma unroll
        for (int q = 0; q < NGRP; ++q) {
            S1 += g_m1[q * P + c];
            S2 += g_m2[q * P + c];
        }
        const float inv  = 1.0f / (float)n_rows;
        const float m    = S1 * inv;
        const float mom2 = S2 * inv - m * m;   // mean((x-m)^2) = S2/N - m^2
        // mom1 = mean(x - m) == 0 exactly with m = S1/N

        const int j0 = 3 * c;
        const float cm0 = m    - mu[j0 + 0];
        const float cm1 = 0.f  - mu[j0 + 1];
        const float cm2 = mom2 - mu[j0 + 2];

        const float* __restrict__ w = W + j0 * 4;   // W is (1728, 4) row-major
        float4 acc;
        acc.x = cm0 * w[0] + cm1 * w[4] + cm2 * w[8];
        acc.y = cm0 * w[1] + cm1 * w[5] + cm2 * w[9];
        acc.z = cm0 * w[2] + cm1 * w[6] + cm2 * w[10];
        acc.w = cm0 * w[3] + cm1 * w[7] + cm2 * w[11];

        float4* red = reinterpret_cast<float4*>(sh);   // 576 float4 = 9216B
        red[c] = acc;
        __syncthreads();

        // 576 = 512 + 64: fold the tail, then power-of-2 tree.
        if (c < 64) {
            float4 o = red[c + 512];
            red[c].x += o.x; red[c].y += o.y; red[c].z += o.z; red[c].w += o.w;
        }
        __syncthreads();
        for (int s = 256; s >= 1; s >>= 1) {
            if (c < s) {
                float4 o = red[c + s];
                red[c].x += o.x; red[c].y += o.y; red[c].z += o.z; red[c].w += o.w;
            }
            __syncthreads();
        }
        if (c == 0) {
            out[0] = red[0].x;
            out[1] = red[0].y;
            out[2] = red[0].z;
            out[3] = red[0].w;
        }

        // Reset counters for the next graph replay. All other blocks have
        // retired past their counter updates (we observed their arrivals),
        // so plain stores here are safe; launch boundary orders vs next run.
        if (c < NGRP) g_cnt1[c] = 0u;
        if (c == 0)   g_cnt2 = 0u;
    }
}

extern "C" void kernel_launch(void* const* d_in, const int* in_sizes, int n_in,
                              void* d_out, int out_size) {
    const float* X  = (const float*)d_in[0];   // (N_ROWS, 576) fp32
    const float* mu = (const float*)d_in[1];   // (1728,)
    const float* W  = (const float*)d_in[2];   // (1728, 4)
    float* out = (float*)d_out;                // (1, 4) fp32

    const int n_rows = in_sizes[0] / P;        // 200000

    k_fused<<<NB, P>>>(X, mu, W, out, n_rows);
}